// round 3
// baseline (speedup 1.0000x reference)
#include <cuda_runtime.h>
#include <math.h>

// GEBLNet fused kernel, round 3.
//  - weights pre-transposed to [w][u*S+v] (coalesced LDG)
//  - swap-trick f32x2 complex MACs: one u64 accumulator per element
//  - layer-2 stage_c: 2 tasks per thread -> W[w] shared-load amortized 2x

#define U    12
#define S1   13
#define S2   25
#define NT   160
#define MS   20
#define NPTF 180
#define T1   (U*S1)      // 156
#define T2   (U*S2)      // 300

typedef unsigned long long u64;

__device__ float g_w1T[S1 * T1 * 2];   // [w][task] complex
__device__ float g_w2T[S2 * T2 * 2];

__device__ __forceinline__ u64 pk(float lo, float hi) {
    u64 r; asm("mov.b64 %0,{%1,%2};" : "=l"(r) : "f"(lo), "f"(hi)); return r;
}
__device__ __forceinline__ void fma2(u64& d, u64 a, u64 b) {
    asm("fma.rn.f32x2 %0,%1,%2,%0;" : "+l"(d) : "l"(a), "l"(b));
}
__device__ __forceinline__ float2 up(u64 a) {
    float2 f; asm("mov.b64 {%0,%1},%2;" : "=f"(f.x), "=f"(f.y) : "l"(a)); return f;
}

__global__ void transpose_w(const float* __restrict__ w1, const float* __restrict__ w2)
{
    int tid = blockIdx.x * blockDim.x + threadIdx.x;
    if (tid < U * S1 * S1) {
        int u = tid / (S1 * S1), r = tid % (S1 * S1), v = r / S1, w = r % S1;
        int dst = w * T1 + u * S1 + v;
        g_w1T[dst * 2 + 0] = w1[tid * 2 + 0];
        g_w1T[dst * 2 + 1] = w1[tid * 2 + 1];
    }
    if (tid < U * S2 * S2) {
        int u = tid / (S2 * S2), r = tid % (S2 * S2), v = r / S2, w = r % S2;
        int dst = w * T2 + u * S2 + v;
        g_w2T[dst * 2 + 0] = w2[tid * 2 + 0];
        g_w2T[dst * 2 + 1] = w2[tid * 2 + 1];
    }
}

// C[u,v]_{e} = sum_w wgt[u,v,w] * W[w]_{e}
// TPT tasks per thread: tasks {tid + h*H}, H = T/TPT. Amortizes the W[w]
// shared broadcast across TPT tasks.
template<int S, int TPT>
__device__ __forceinline__ void stage_c(const float* __restrict__ wT,
                                        const float* __restrict__ sW,
                                        u64* __restrict__ sC, int tid)
{
    const int T = U * S;
    const int H = T / TPT;
    if (tid < H) {
        u64 acc[TPT][9];
#pragma unroll
        for (int t = 0; t < TPT; t++)
#pragma unroll
            for (int e = 0; e < 9; e++) acc[t][e] = 0ull;

        const float2* wbase = reinterpret_cast<const float2*>(wT);
        for (int w = 0; w < S; ++w) {
            // broadcast load of W[w] (72 B, 5 LDS)
            const float4* m4 = reinterpret_cast<const float4*>(sW + w * MS);
            float4 f0 = m4[0], f1 = m4[1], f2 = m4[2], f3 = m4[3];
            float2 ft = *reinterpret_cast<const float2*>(sW + w * MS + 16);
            float blo[9], bhi[9];
            blo[0]=f0.x; bhi[0]=f0.y;  blo[1]=f0.z; bhi[1]=f0.w;
            blo[2]=f1.x; bhi[2]=f1.y;  blo[3]=f1.z; bhi[3]=f1.w;
            blo[4]=f2.x; bhi[4]=f2.y;  blo[5]=f2.z; bhi[5]=f2.w;
            blo[6]=f3.x; bhi[6]=f3.y;  blo[7]=ft.x; bhi[7]=ft.y;
            // note: element 8 below
            float b8lo, b8hi;
            {
                float2 f8 = *reinterpret_cast<const float2*>(sW + w * MS + 16);
                (void)f8;
            }
            blo[8] = 0.f; bhi[8] = 0.f;   // placeholder, fixed below

            // careful: 18 floats = f0..f3 (16) + ft (2): elements 0..7 from f0..f3,
            // element 8 from ft. Re-map properly:
            blo[8] = ft.x; bhi[8] = ft.y;
            blo[7] = f3.z; bhi[7] = f3.w;

            u64 wr[TPT], wi[TPT];
#pragma unroll
            for (int t = 0; t < TPT; t++) {
                float2 wv = __ldg(wbase + w * T + tid + t * H);
                wr[t] = pk(wv.x, wv.x);
                wi[t] = pk(-wv.y, wv.y);
            }
#pragma unroll
            for (int e = 0; e < 9; e++) {
                u64 b  = pk(blo[e], bhi[e]);
                u64 bs = pk(bhi[e], blo[e]);
#pragma unroll
                for (int t = 0; t < TPT; t++) {
                    fma2(acc[t][e], wr[t], b);   // {wr*br, wr*bi}
                    fma2(acc[t][e], wi[t], bs);  // {-wi*bi, wi*br}
                }
            }
        }
#pragma unroll
        for (int t = 0; t < TPT; t++)
#pragma unroll
            for (int e = 0; e < 9; e++)
                sC[e * T + tid + t * H] = acc[t][e];
    }
}

// wout[u]_{ik} = sum_{v,j} W[v]_{ij} * C[u,v]_{jk}
template<int S>
__device__ __forceinline__ void stage_m(const float* __restrict__ sW,
                                        const u64* __restrict__ sC,
                                        float* __restrict__ sM, int tid)
{
    const int T = U * S;
    if (tid < U * 9) {
        int u = tid / 9, e = tid % 9;
        int i = e / 3, k = e % 3;
        u64 acc = 0ull;
        for (int v = 0; v < S; ++v) {
            const float* Wv = sW + v * MS + i * 6;
            const u64*  Cv = sC + u * S + v;
#pragma unroll
            for (int j = 0; j < 3; ++j) {
                float br = Wv[2*j], bi = Wv[2*j + 1];
                float2 c = up(Cv[(j * 3 + k) * T]);
                fma2(acc, pk(br, br),  pk(c.x, c.y));
                fma2(acc, pk(-bi, bi), pk(c.y, c.x));
            }
        }
        float2 p = up(acc);
        sM[u * MS + 2*e]     = p.x;
        sM[u * MS + 2*e + 1] = p.y;
    }
}

__global__ __launch_bounds__(NT, 5)
void gebl_kernel(const float* __restrict__ x,
                 const float* __restrict__ dw,
                 const float* __restrict__ db,
                 float* __restrict__ out)
{
    __shared__ __align__(16) float sW[S2 * MS];
    __shared__ u64   sC[9 * T2];
    __shared__ float sM[U * MS];
    __shared__ float sTrRe[U], sTrIm[U], sAbs[U], sScale[U];

    const int tid   = threadIdx.x;
    const int point = blockIdx.x;
    const float* xp = x + (size_t)point * NPTF + 4 * 18;

    // ---- Build W1 (6 orig + 6 conj-transpose + identity) ----
    for (int idx = tid; idx < 6 * 18; idx += NT) {
        int ch = idx / 18, r = idx % 18;
        sW[ch * MS + r] = xp[idx];
    }
    for (int idx = tid; idx < 6 * 18; idx += NT) {
        int ch = idx / 18, r = idx % 18;
        int e = r >> 1, comp = r & 1;
        int i = e / 3, j = e % 3;
        float v = xp[ch * 18 + (j * 3 + i) * 2 + comp];
        sW[(6 + ch) * MS + r] = comp ? -v : v;
    }
    if (tid < 18) {
        int e = tid >> 1, comp = tid & 1;
        sW[12 * MS + tid] = (comp == 0 && (e % 4) == 0) ? 1.0f : 0.0f;
    }
    __syncthreads();

    // ---- Layer 1 ----
    stage_c<S1, 1>(g_w1T, sW, sC, tid);
    __syncthreads();
    stage_m<S1>(sW, sC, sM, tid);
    __syncthreads();

    if (tid < U) {
        float trRe = sM[tid*MS + 0] + sM[tid*MS + 8] + sM[tid*MS + 16];
        float trIm = sM[tid*MS + 1] + sM[tid*MS + 9] + sM[tid*MS + 17];
        float t = fmaxf(trRe, 0.0f);
        sAbs[tid]   = t * sqrtf(trRe * trRe + trIm * trIm);
        sScale[tid] = t;
    }
    __syncthreads();
    if (tid == 0) {
        float s = 0.f;
#pragma unroll
        for (int u = 0; u < U; u++) s += sAbs[u];
        sAbs[0] = fmaxf(s * (1.0f / U), 0.001f);
    }
    __syncthreads();
    const float inv_norm1 = 1.0f / sAbs[0];
    __syncthreads();

    // ---- Build W2 ----
    for (int idx = tid; idx < U * 18; idx += NT) {
        int ch = idx / 18, r = idx % 18;
        sW[ch * MS + r] = sM[ch * MS + r] * (sScale[ch] * inv_norm1);
    }
    for (int idx = tid; idx < U * 18; idx += NT) {
        int ch = idx / 18, r = idx % 18;
        int e = r >> 1, comp = r & 1;
        int i = e / 3, j = e % 3;
        float v = sM[ch * MS + (j * 3 + i) * 2 + comp] * (sScale[ch] * inv_norm1);
        sW[(U + ch) * MS + r] = comp ? -v : v;
    }
    if (tid < 18) {
        int e = tid >> 1, comp = tid & 1;
        sW[24 * MS + tid] = (comp == 0 && (e % 4) == 0) ? 1.0f : 0.0f;
    }
    __syncthreads();

    // ---- Layer 2 (2 tasks/thread) ----
    stage_c<S2, 2>(g_w2T, sW, sC, tid);
    __syncthreads();
    stage_m<S2>(sW, sC, sM, tid);
    __syncthreads();

    // ---- Layer-2 scalars + head ----
    if (tid < U) {
        float trRe = sM[tid*MS + 0] + sM[tid*MS + 8] + sM[tid*MS + 16];
        float trIm = sM[tid*MS + 1] + sM[tid*MS + 9] + sM[tid*MS + 17];
        float t = fmaxf(trRe, 0.0f);
        sTrRe[tid]  = trRe;
        sTrIm[tid]  = trIm;
        sAbs[tid]   = t * sqrtf(trRe * trRe + trIm * trIm);
        sScale[tid] = t;
    }
    __syncthreads();
    if (tid == 0) {
        float s = 0.f;
#pragma unroll
        for (int u = 0; u < U; u++) s += sAbs[u];
        float norm = fmaxf(s * (1.0f / U), 0.001f);
        float o = __ldg(&db[0]);
#pragma unroll
        for (int u = 0; u < U; u++) {
            float sc = sScale[u] / norm * (1.0f / 3.0f);
            o = fmaf(sc * sTrRe[u], __ldg(&dw[2*u]),     o);
            o = fmaf(sc * sTrIm[u], __ldg(&dw[2*u + 1]), o);
        }
        out[point] = o;
    }
}

extern "C" void kernel_launch(void* const* d_in, const int* in_sizes, int n_in,
                              void* d_out, int out_size)
{
    const float* x  = (const float*)d_in[0];
    const float* w1 = (const float*)d_in[1];
    const float* w2 = (const float*)d_in[2];
    const float* dw = (const float*)d_in[3];
    const float* db = (const float*)d_in[4];
    float* out = (float*)d_out;

    int points = in_sizes[0] / NPTF;   // 8192

    transpose_w<<<(U*S2*S2 + 255) / 256, 256>>>(w1, w2);
    gebl_kernel<<<points, NT>>>(x, dw, db, out);
}

// round 4
// speedup vs baseline: 1.1481x; 1.1481x over previous
#include <cuda_runtime.h>
#include <math.h>

// GEBLNet fused kernel, round 4.
//  - swap-trick operands stored IN SHARED as ulonglong2 {b, bs} (zero movs)
//  - conj-transpose channel fold: stage_c w-loop over 6/12 base matrices only
//    (A + conj(E^T) + c*I), halving LDS + W-build at equal FMA
//  - weights pre-split into A/E(conj)/C arrays, task-major (coalesced LDG)

#define U    12
#define S1   13
#define S2   25
#define NB1  6
#define NB2  12
#define T1   (U*S1)      // 156
#define T2   (U*S2)      // 300
#define NT   160
#define NPTF 180

typedef unsigned long long u64;

__device__ float2 g_A1[NB1*T1], g_E1[NB1*T1], g_C1[T1];
__device__ float2 g_A2[NB2*T2], g_E2[NB2*T2], g_C2[T2];

__device__ __forceinline__ u64 pk(float lo, float hi) {
    u64 r; asm("mov.b64 %0,{%1,%2};" : "=l"(r) : "f"(lo), "f"(hi)); return r;
}
__device__ __forceinline__ void fma2(u64& d, u64 a, u64 b) {
    asm("fma.rn.f32x2 %0,%1,%2,%0;" : "+l"(d) : "l"(a), "l"(b));
}
__device__ __forceinline__ u64 mul2(u64 a, u64 b) {
    u64 r; asm("mul.rn.f32x2 %0,%1,%2;" : "=l"(r) : "l"(a), "l"(b)); return r;
}
__device__ __forceinline__ float2 up(u64 a) {
    float2 f; asm("mov.b64 {%0,%1},%2;" : "=f"(f.x), "=f"(f.y) : "l"(a)); return f;
}

// Split weights: A = g[0..NB), E = conj(g[NB..2NB)), C = g[2NB]; task-major.
__global__ void prep_w(const float* __restrict__ w1, const float* __restrict__ w2)
{
    int t = blockIdx.x * blockDim.x + threadIdx.x;
    if (t < T1) {
        const float* b = w1 + (size_t)t * S1 * 2;
        for (int w = 0; w < NB1; w++) {
            g_A1[w*T1 + t] = make_float2(b[2*w],          b[2*w + 1]);
            g_E1[w*T1 + t] = make_float2(b[2*(NB1+w)],   -b[2*(NB1+w) + 1]);
        }
        g_C1[t] = make_float2(b[2*(2*NB1)], b[2*(2*NB1) + 1]);
    }
    if (t < T2) {
        const float* b = w2 + (size_t)t * S2 * 2;
        for (int w = 0; w < NB2; w++) {
            g_A2[w*T2 + t] = make_float2(b[2*w],          b[2*w + 1]);
            g_E2[w*T2 + t] = make_float2(b[2*(NB2+w)],   -b[2*(NB2+w) + 1]);
        }
        g_C2[t] = make_float2(b[2*(2*NB2)], b[2*(2*NB2) + 1]);
    }
}

// C[u,v] = sum_{w<NB} a_w*W[w]  +  conj( sum_{w<NB} e_w*W[w] )^T  +  c*I
template<int S, int NB>
__device__ __forceinline__ void stage_c(const float2* __restrict__ gA,
                                        const float2* __restrict__ gE,
                                        const float2* __restrict__ gC,
                                        const ulonglong2* __restrict__ sWp,
                                        u64* __restrict__ sC, int tid)
{
    const int T = U * S;
    for (int task = tid; task < T; task += NT) {
        u64 A[9], E[9];
#pragma unroll
        for (int e = 0; e < 9; e++) { A[e] = 0ull; E[e] = 0ull; }

        for (int w = 0; w < NB; ++w) {
            float2 aw = __ldg(gA + w*T + task);
            float2 ew = __ldg(gE + w*T + task);
            u64 ar = pk(aw.x, aw.x), ai = pk(aw.y, aw.y);
            u64 er = pk(ew.x, ew.x), ei = pk(ew.y, ew.y);
#pragma unroll
            for (int e = 0; e < 9; e++) {
                ulonglong2 bp = sWp[w*9 + e];   // {b={re,im}, bs={-im,re}}
                fma2(A[e], ar, bp.x);
                fma2(A[e], ai, bp.y);
                fma2(E[e], er, bp.x);
                fma2(E[e], ei, bp.y);
            }
        }
        // combine: C[(i,k)] = A[(i,k)] + {1,-1} ⊙ E[(k,i)]  (+ c on diagonal)
        const u64 pm = pk(1.0f, -1.0f);
        u64 C[9];
#pragma unroll
        for (int i = 0; i < 3; i++)
#pragma unroll
            for (int k = 0; k < 3; k++) {
                int e = i*3 + k, et = k*3 + i;
                u64 r = A[e];
                fma2(r, pm, E[et]);
                C[e] = r;
            }
        float2 cw = __ldg(gC + task);
        const u64 one2 = pk(1.0f, 1.0f);
        u64 cc = pk(cw.x, cw.y);
        fma2(C[0], one2, cc);
        fma2(C[4], one2, cc);
        fma2(C[8], one2, cc);
#pragma unroll
        for (int e = 0; e < 9; e++) sC[e*T + task] = C[e];
    }
}

// wout[u](i,k) = sum_{v<NB} W[v](i,:)C[u,v](:,k)
//             + sum_{v<NB} conj(W[v](:,i))^T C[u,NB+v](:,k)
//             + C[u,2NB](i,k)
template<int S, int NB>
__device__ __forceinline__ void stage_m(const ulonglong2* __restrict__ sWp,
                                        const u64* __restrict__ sC,
                                        u64* __restrict__ sM, int tid)
{
    const int T = U * S;
    if (tid < U * 9) {
        int u = tid / 9, e = tid % 9;
        int i = e / 3, k = e % 3;
        u64 a1 = 0ull, a2 = 0ull, a2c = 0ull;
        const u64* Cu = sC + u * S;
        for (int v = 0; v < NB; ++v) {
#pragma unroll
            for (int j = 0; j < 3; ++j) {
                float2 b = up(sWp[v*9 + i*3 + j].x);     // W[v](i,j)
                u64 c = Cu[(j*3 + k)*T + v];
                fma2(a1, pk(b.x, b.x), c);
                fma2(a2, pk(b.y, b.y), c);
            }
        }
        for (int v = 0; v < NB; ++v) {
#pragma unroll
            for (int j = 0; j < 3; ++j) {
                float2 b = up(sWp[v*9 + j*3 + i].x);     // base(j,i); conj applied in combine
                u64 c = Cu[(j*3 + k)*T + NB + v];
                fma2(a1,  pk(b.x, b.x), c);
                fma2(a2c, pk(b.y, b.y), c);
            }
        }
        float2 p = up(a1), q = up(a2), qc = up(a2c);
        float2 ci = up(Cu[(i*3 + k)*T + 2*NB]);          // identity channel
        sM[u*9 + e] = pk(p.x - q.y + qc.y + ci.x,
                         p.y + q.x - qc.x + ci.y);
    }
}

__global__ __launch_bounds__(NT, 5)
void gebl_kernel(const float* __restrict__ x,
                 const float* __restrict__ dw,
                 const float* __restrict__ db,
                 float* __restrict__ out)
{
    __shared__ __align__(16) ulonglong2 sWp[NB2 * 9];   // base matrices {b,bs}: 1728 B
    __shared__ u64   sC[9 * T2];                        // 21600 B
    __shared__ u64   sM[U * 9];                         // 864 B
    __shared__ float sTrRe[U], sTrIm[U], sAbs[U], sScale[U];
    __shared__ float sNormInv;

    const int tid   = threadIdx.x;
    const int point = blockIdx.x;
    const float2* xp = reinterpret_cast<const float2*>(x + (size_t)point * NPTF) + 4 * 9;

    // ---- Build base W1 (6 matrices, interleaved {b, bs}) ----
    if (tid < NB1 * 9) {
        float2 v = __ldg(xp + tid);
        sWp[tid] = make_ulonglong2(pk(v.x, v.y), pk(-v.y, v.x));
    }
    __syncthreads();

    // ---- Layer 1 ----
    stage_c<S1, NB1>(g_A1, g_E1, g_C1, sWp, sC, tid);
    __syncthreads();
    stage_m<S1, NB1>(sWp, sC, sM, tid);
    __syncthreads();

    if (tid < U) {
        float2 t0 = up(sM[tid*9 + 0]), t4 = up(sM[tid*9 + 4]), t8 = up(sM[tid*9 + 8]);
        float trRe = t0.x + t4.x + t8.x;
        float trIm = t0.y + t4.y + t8.y;
        float t = fmaxf(trRe, 0.0f);
        sAbs[tid]   = t * sqrtf(trRe*trRe + trIm*trIm);
        sScale[tid] = t;
    }
    __syncthreads();
    if (tid == 0) {
        float s = 0.f;
#pragma unroll
        for (int u = 0; u < U; u++) s += sAbs[u];
        sNormInv = 1.0f / fmaxf(s * (1.0f / U), 0.001f);
    }
    __syncthreads();

    // ---- Build base W2 (12 scaled matrices) ----
    if (tid < U * 9) {
        int ch = tid / 9;
        float s = sScale[ch] * sNormInv;
        float2 m = up(sM[tid]);
        sWp[tid] = make_ulonglong2(pk(s*m.x, s*m.y), pk(-s*m.y, s*m.x));
    }
    __syncthreads();

    // ---- Layer 2 ----
    stage_c<S2, NB2>(g_A2, g_E2, g_C2, sWp, sC, tid);
    __syncthreads();
    stage_m<S2, NB2>(sWp, sC, sM, tid);
    __syncthreads();

    // ---- Layer-2 scalars + head ----
    if (tid < U) {
        float2 t0 = up(sM[tid*9 + 0]), t4 = up(sM[tid*9 + 4]), t8 = up(sM[tid*9 + 8]);
        float trRe = t0.x + t4.x + t8.x;
        float trIm = t0.y + t4.y + t8.y;
        float t = fmaxf(trRe, 0.0f);
        sTrRe[tid]  = trRe;
        sTrIm[tid]  = trIm;
        sAbs[tid]   = t * sqrtf(trRe*trRe + trIm*trIm);
        sScale[tid] = t;
    }
    __syncthreads();
    if (tid == 0) {
        float s = 0.f;
#pragma unroll
        for (int u = 0; u < U; u++) s += sAbs[u];
        float inv_norm = 1.0f / fmaxf(s * (1.0f / U), 0.001f);
        float o = __ldg(&db[0]);
#pragma unroll
        for (int u = 0; u < U; u++) {
            float sc = sScale[u] * inv_norm * (1.0f / 3.0f);
            o = fmaf(sc * sTrRe[u], __ldg(&dw[2*u]),     o);
            o = fmaf(sc * sTrIm[u], __ldg(&dw[2*u + 1]), o);
        }
        out[point] = o;
    }
}

extern "C" void kernel_launch(void* const* d_in, const int* in_sizes, int n_in,
                              void* d_out, int out_size)
{
    const float* x  = (const float*)d_in[0];
    const float* w1 = (const float*)d_in[1];
    const float* w2 = (const float*)d_in[2];
    const float* dw = (const float*)d_in[3];
    const float* db = (const float*)d_in[4];
    float* out = (float*)d_out;

    int points = in_sizes[0] / NPTF;   // 8192

    prep_w<<<1, 320>>>(w1, w2);
    gebl_kernel<<<points, NT>>>(x, dw, db, out);
}

// round 5
// speedup vs baseline: 1.1664x; 1.0160x over previous
#include <cuda_runtime.h>
#include <math.h>

// GEBLNet fused kernel, round 5.
//  - single-accumulator stage_c: conj-transpose channel folded inline via
//    sign-carrying f32x2 packs ({er,-er},{-ei,ei} come free from a float4 LDG)
//  - swap-trick operands {b, bs} live in shared (ulonglong2, zero movs)
//  - layer-2 stage_c: 2 tasks/thread -> 9 bp shared loads amortized 2x

#define U    12
#define S1   13
#define S2   25
#define NB1  6
#define NB2  12
#define T1   (U*S1)      // 156
#define T2   (U*S2)      // 300
#define NT   160
#define NPTF 180

typedef unsigned long long u64;

__device__ float2 g_A1[NB1*T1], g_C1[T1];
__device__ float2 g_A2[NB2*T2], g_C2[T2];
__device__ float4 g_E1[NB1*T1];            // {er, -er, -ei, ei}
__device__ float4 g_E2[NB2*T2];

__device__ __forceinline__ u64 pk(float lo, float hi) {
    u64 r; asm("mov.b64 %0,{%1,%2};" : "=l"(r) : "f"(lo), "f"(hi)); return r;
}
__device__ __forceinline__ void fma2(u64& d, u64 a, u64 b) {
    asm("fma.rn.f32x2 %0,%1,%2,%0;" : "+l"(d) : "l"(a), "l"(b));
}
__device__ __forceinline__ float2 up(u64 a) {
    float2 f; asm("mov.b64 {%0,%1},%2;" : "=f"(f.x), "=f"(f.y) : "l"(a)); return f;
}

__global__ void prep_w(const float* __restrict__ w1, const float* __restrict__ w2)
{
    int t = blockIdx.x * blockDim.x + threadIdx.x;
    if (t < T1) {
        const float* b = w1 + (size_t)t * S1 * 2;
        for (int w = 0; w < NB1; w++) {
            g_A1[w*T1 + t] = make_float2(b[2*w], b[2*w + 1]);
            float er = b[2*(NB1+w)], ei = b[2*(NB1+w) + 1];
            g_E1[w*T1 + t] = make_float4(er, -er, -ei, ei);
        }
        g_C1[t] = make_float2(b[2*(2*NB1)], b[2*(2*NB1) + 1]);
    }
    if (t < T2) {
        const float* b = w2 + (size_t)t * S2 * 2;
        for (int w = 0; w < NB2; w++) {
            g_A2[w*T2 + t] = make_float2(b[2*w], b[2*w + 1]);
            float er = b[2*(NB2+w)], ei = b[2*(NB2+w) + 1];
            g_E2[w*T2 + t] = make_float4(er, -er, -ei, ei);
        }
        g_C2[t] = make_float2(b[2*(2*NB2)], b[2*(2*NB2) + 1]);
    }
}

// C[u,v] = sum_w a_w*W[w] + sum_w e_w*W[w]^H + c*I, single accumulator.
//   acc[(i,k)] += {ar,ar}.b[(i,k)] + {ai,ai}.bs[(i,k)]
//              + {er,-er}.b[(k,i)] + {-ei,ei}.bs[(k,i)]
template<int S, int NB, int TPT>
__device__ __forceinline__ void stage_c(const float2* __restrict__ gA,
                                        const float4* __restrict__ gE,
                                        const float2* __restrict__ gC,
                                        const ulonglong2* __restrict__ sWp,
                                        u64* __restrict__ sC, int tid)
{
    const int T = U * S;
    const int H = T / TPT;
    if (tid < H) {
        u64 acc[TPT][9];
#pragma unroll
        for (int t = 0; t < TPT; t++)
#pragma unroll
            for (int e = 0; e < 9; e++) acc[t][e] = 0ull;

#pragma unroll
        for (int w = 0; w < NB; ++w) {
            ulonglong2 bp[9];
#pragma unroll
            for (int e = 0; e < 9; e++) bp[e] = sWp[w*9 + e];   // {b, bs}

#pragma unroll
            for (int t = 0; t < TPT; t++) {
                int task = tid + t * H;
                float2 aw = __ldg(gA + w*T + task);
                float4 ef = __ldg(gE + w*T + task);
                u64 ar = pk(aw.x, aw.x), ai = pk(aw.y, aw.y);
                u64 er = pk(ef.x, ef.y), ei = pk(ef.z, ef.w);   // free pairs
#pragma unroll
                for (int i = 0; i < 3; i++)
#pragma unroll
                    for (int k = 0; k < 3; k++) {
                        int e = i*3 + k, et = k*3 + i;
                        fma2(acc[t][e], ar, bp[e].x);
                        fma2(acc[t][e], ai, bp[e].y);
                        fma2(acc[t][e], er, bp[et].x);
                        fma2(acc[t][e], ei, bp[et].y);
                    }
            }
        }
        const u64 one2 = pk(1.0f, 1.0f);
#pragma unroll
        for (int t = 0; t < TPT; t++) {
            int task = tid + t * H;
            float2 cw = __ldg(gC + task);
            u64 cc = pk(cw.x, cw.y);
            fma2(acc[t][0], one2, cc);
            fma2(acc[t][4], one2, cc);
            fma2(acc[t][8], one2, cc);
#pragma unroll
            for (int e = 0; e < 9; e++) sC[e*T + task] = acc[t][e];
        }
    }
}

// wout[u](i,k) = sum_{v<NB} W[v](i,:)C[u,v](:,k)
//             + sum_{v<NB} W[v]^H(i,:)C[u,NB+v](:,k) + C[u,2NB](i,k)
template<int S, int NB>
__device__ __forceinline__ void stage_m(const ulonglong2* __restrict__ sWp,
                                        const u64* __restrict__ sC,
                                        u64* __restrict__ sM, int tid)
{
    const int T = U * S;
    if (tid < U * 9) {
        int u = tid / 9, e = tid % 9;
        int i = e / 3, k = e % 3;
        u64 a1 = 0ull, a2 = 0ull, a2c = 0ull;
        const u64* Cu = sC + u * S;
#pragma unroll
        for (int v = 0; v < NB; ++v) {
#pragma unroll
            for (int j = 0; j < 3; ++j) {
                float2 b = up(sWp[v*9 + i*3 + j].x);     // W[v](i,j)
                u64 c = Cu[(j*3 + k)*T + v];
                fma2(a1, pk(b.x, b.x), c);
                fma2(a2, pk(b.y, b.y), c);
            }
        }
#pragma unroll
        for (int v = 0; v < NB; ++v) {
#pragma unroll
            for (int j = 0; j < 3; ++j) {
                float2 b = up(sWp[v*9 + j*3 + i].x);     // base(j,i)
                u64 c = Cu[(j*3 + k)*T + NB + v];
                fma2(a1,  pk(b.x, b.x), c);
                fma2(a2c, pk(b.y, b.y), c);
            }
        }
        float2 p = up(a1), q = up(a2), qc = up(a2c);
        float2 ci = up(Cu[(i*3 + k)*T + 2*NB]);          // identity channel
        sM[u*9 + e] = pk(p.x - q.y + qc.y + ci.x,
                         p.y + q.x - qc.x + ci.y);
    }
}

__global__ __launch_bounds__(NT, 4)
void gebl_kernel(const float* __restrict__ x,
                 const float* __restrict__ dw,
                 const float* __restrict__ db,
                 float* __restrict__ out)
{
    __shared__ __align__(16) ulonglong2 sWp[NB2 * 9];   // 1728 B
    __shared__ u64   sC[9 * T2];                        // 21600 B
    __shared__ u64   sM[U * 9];                         // 864 B
    __shared__ float sTrRe[U], sTrIm[U], sAbs[U], sScale[U];
    __shared__ float sNormInv;

    const int tid   = threadIdx.x;
    const int point = blockIdx.x;
    const float2* xp = reinterpret_cast<const float2*>(x + (size_t)point * NPTF) + 4 * 9;

    // ---- Build base W1 (6 matrices, interleaved {b, bs}) ----
    if (tid < NB1 * 9) {
        float2 v = __ldg(xp + tid);
        sWp[tid] = make_ulonglong2(pk(v.x, v.y), pk(-v.y, v.x));
    }
    __syncthreads();

    // ---- Layer 1 ----
    stage_c<S1, NB1, 1>(g_A1, g_E1, g_C1, sWp, sC, tid);
    __syncthreads();
    stage_m<S1, NB1>(sWp, sC, sM, tid);
    __syncthreads();

    if (tid < U) {
        float2 t0 = up(sM[tid*9 + 0]), t4 = up(sM[tid*9 + 4]), t8 = up(sM[tid*9 + 8]);
        float trRe = t0.x + t4.x + t8.x;
        float trIm = t0.y + t4.y + t8.y;
        float t = fmaxf(trRe, 0.0f);
        sAbs[tid]   = t * sqrtf(trRe*trRe + trIm*trIm);
        sScale[tid] = t;
    }
    __syncthreads();
    if (tid == 0) {
        float s = 0.f;
#pragma unroll
        for (int u = 0; u < U; u++) s += sAbs[u];
        sNormInv = 1.0f / fmaxf(s * (1.0f / U), 0.001f);
    }
    __syncthreads();

    // ---- Build base W2 (12 scaled matrices) ----
    if (tid < U * 9) {
        int ch = tid / 9;
        float s = sScale[ch] * sNormInv;
        float2 m = up(sM[tid]);
        sWp[tid] = make_ulonglong2(pk(s*m.x, s*m.y), pk(-s*m.y, s*m.x));
    }
    __syncthreads();

    // ---- Layer 2 (2 tasks/thread) ----
    stage_c<S2, NB2, 2>(g_A2, g_E2, g_C2, sWp, sC, tid);
    __syncthreads();
    stage_m<S2, NB2>(sWp, sC, sM, tid);
    __syncthreads();

    // ---- Layer-2 scalars + head ----
    if (tid < U) {
        float2 t0 = up(sM[tid*9 + 0]), t4 = up(sM[tid*9 + 4]), t8 = up(sM[tid*9 + 8]);
        float trRe = t0.x + t4.x + t8.x;
        float trIm = t0.y + t4.y + t8.y;
        float t = fmaxf(trRe, 0.0f);
        sTrRe[tid]  = trRe;
        sTrIm[tid]  = trIm;
        sAbs[tid]   = t * sqrtf(trRe*trRe + trIm*trIm);
        sScale[tid] = t;
    }
    __syncthreads();
    if (tid == 0) {
        float s = 0.f;
#pragma unroll
        for (int u = 0; u < U; u++) s += sAbs[u];
        float inv_norm = 1.0f / fmaxf(s * (1.0f / U), 0.001f);
        float o = __ldg(&db[0]);
#pragma unroll
        for (int u = 0; u < U; u++) {
            float sc = sScale[u] * inv_norm * (1.0f / 3.0f);
            o = fmaf(sc * sTrRe[u], __ldg(&dw[2*u]),     o);
            o = fmaf(sc * sTrIm[u], __ldg(&dw[2*u + 1]), o);
        }
        out[point] = o;
    }
}

extern "C" void kernel_launch(void* const* d_in, const int* in_sizes, int n_in,
                              void* d_out, int out_size)
{
    const float* x  = (const float*)d_in[0];
    const float* w1 = (const float*)d_in[1];
    const float* w2 = (const float*)d_in[2];
    const float* dw = (const float*)d_in[3];
    const float* db = (const float*)d_in[4];
    float* out = (float*)d_out;

    int points = in_sizes[0] / NPTF;   // 8192

    prep_w<<<1, 320>>>(w1, w2);
    gebl_kernel<<<points, NT>>>(x, dw, db, out);
}